// round 7
// baseline (speedup 1.0000x reference)
#include <cuda_runtime.h>
#include <cuda_bf16.h>
#include <cstdint>

#define BS      16
#define SEQ     512
#define HID     768
#define HEADS   12
#define HDIM    64
#define M1      (BS*SEQ)          // 8192
#define N1      (HEADS*2*HDIM)    // 1536
#define K1      HID               // 768
#define NEG_BIG 1e12f

#define SROW    40                 // padded smem row stride (elements), 80B
#define GBK     32
#define ITERS   (K1/GBK)           // 24
#define STAGES  3
#define TM      256
#define TN      128
#define A_BYTES (TM*SROW*2)        // 20480
#define B_BYTES (TN*SROW*2)        // 10240
#define STAGE_B (A_BYTES + B_BYTES)
#define DYN_SMEM (STAGES*STAGE_B)  // 92160

// ---------------- scratch ----------------
__device__ __nv_bfloat16 g_hidden_bf[M1 * K1];
__device__ __nv_bfloat16 g_Wt[N1 * K1];                 // W transposed [n][k]
__device__ __nv_bfloat16 g_q[BS * HEADS * SEQ * HDIM];  // [b][h][s][d]
__device__ __nv_bfloat16 g_k[BS * HEADS * SEQ * HDIM];
__device__ float2        g_sc[SEQ * (HDIM/2)];

// ---------------- helpers ----------------
__device__ __forceinline__ void mma_bf16(float* c, const unsigned* a, unsigned b0, unsigned b1) {
    asm volatile(
        "mma.sync.aligned.m16n8k16.row.col.f32.bf16.bf16.f32 "
        "{%0,%1,%2,%3}, {%4,%5,%6,%7}, {%8,%9}, {%0,%1,%2,%3};\n"
        : "+f"(c[0]), "+f"(c[1]), "+f"(c[2]), "+f"(c[3])
        : "r"(a[0]), "r"(a[1]), "r"(a[2]), "r"(a[3]), "r"(b0), "r"(b1));
}

__device__ __forceinline__ void ldsm_x4(unsigned& r0, unsigned& r1, unsigned& r2, unsigned& r3,
                                        uint32_t addr) {
    asm volatile("ldmatrix.sync.aligned.m8n8.x4.shared.b16 {%0,%1,%2,%3}, [%4];\n"
                 : "=r"(r0), "=r"(r1), "=r"(r2), "=r"(r3) : "r"(addr));
}

__device__ __forceinline__ void cp16(uint32_t s, const void* g) {
    asm volatile("cp.async.cg.shared.global [%0], [%1], 16;\n" :: "r"(s), "l"(g));
}

// ---------------- prep kernels ----------------
__global__ void conv_hidden_kernel(const float* __restrict__ src) {
    int i = (blockIdx.x * blockDim.x + threadIdx.x) * 4;
    if (i >= M1 * K1) return;
    float4 v = *(const float4*)(src + i);
    __nv_bfloat162 p0, p1;
    p0.x = __float2bfloat16(v.x); p0.y = __float2bfloat16(v.y);
    p1.x = __float2bfloat16(v.z); p1.y = __float2bfloat16(v.w);
    uint2 u; u.x = *(unsigned*)&p0; u.y = *(unsigned*)&p1;
    *(uint2*)(g_hidden_bf + i) = u;
}

__global__ void conv_w_kernel(const float* __restrict__ src) {
    __shared__ float tile[32][33];
    int n0 = blockIdx.x * 32, k0 = blockIdx.y * 32;
    int tx = threadIdx.x, ty = threadIdx.y;
#pragma unroll
    for (int i = 0; i < 32; i += 8)
        tile[ty + i][tx] = src[(size_t)(k0 + ty + i) * N1 + n0 + tx];
    __syncthreads();
#pragma unroll
    for (int i = 0; i < 32; i += 8)
        g_Wt[(size_t)(n0 + ty + i) * K1 + k0 + tx] = __float2bfloat16(tile[tx][ty + i]);
}

__global__ void rope_table_kernel() {
    int i = blockIdx.x * blockDim.x + threadIdx.x;
    if (i >= SEQ * (HDIM/2)) return;
    int pos = i >> 5, fi = i & 31;
    float inv = expf(-(float)fi * 0.28782313662425576f);
    float ang = (float)pos * inv;
    float s, c;
    sincosf(ang, &s, &c);
    g_sc[i] = make_float2(c, s);
}

// ---------------- GEMM1: 256x128 block, warp 64x64, 3-stage, 1 sync/iter ----------------
__global__ __launch_bounds__(256, 1) void gemm1_kernel(const float* __restrict__ bias) {
    extern __shared__ __nv_bfloat16 sm[];   // [STAGES][A 256*SROW | B 128*SROW]

    const int tid = threadIdx.x;
    const int wid = tid >> 5, lane = tid & 31;
    const int warp_m = wid & 3, warp_n = wid >> 2;    // 4m x 2n, warp 64x64
    const int g = lane >> 2, tg = lane & 3;
    const int m0 = blockIdx.y * TM, n0 = blockIdx.x * TN;

    float acc[4][8][4];
#pragma unroll
    for (int a = 0; a < 4; a++)
#pragma unroll
        for (int b = 0; b < 8; b++)
#pragma unroll
            for (int c = 0; c < 4; c++) acc[a][b][c] = 0.f;

    const int r0 = tid >> 2, seg = tid & 3;
    const __nv_bfloat16* agp = g_hidden_bf + (size_t)(m0 + r0) * K1 + seg * 8;
    const __nv_bfloat16* bgp = g_Wt       + (size_t)(n0 + r0) * K1 + seg * 8;
    const uint32_t smem0 = (uint32_t)__cvta_generic_to_shared(sm);
    const uint32_t stoff = r0 * (SROW * 2) + seg * 16;

#define G1_ISSUE(stg, kk)  do {                                            \
        uint32_t a = smem0 + (uint32_t)(stg) * STAGE_B + stoff;            \
        uint32_t b = a + A_BYTES;                                          \
        cp16(a,                  agp + (kk));                              \
        cp16(a +  64*(SROW*2),   agp + (size_t) 64*K1 + (kk));             \
        cp16(a + 128*(SROW*2),   agp + (size_t)128*K1 + (kk));             \
        cp16(a + 192*(SROW*2),   agp + (size_t)192*K1 + (kk));             \
        cp16(b,                  bgp + (kk));                              \
        cp16(b +  64*(SROW*2),   bgp + (size_t) 64*K1 + (kk));             \
        asm volatile("cp.async.commit_group;\n");                          \
    } while (0)

    G1_ISSUE(0, 0);
    G1_ISSUE(1, GBK);

    const int a_row = warp_m * 64 + (lane & 15);
    const int a_col = (lane >> 4) * 8;
    const int b_row = warp_n * 64 + (lane & 7) + ((lane >> 4) << 3);
    const int b_col = ((lane >> 3) & 1) * 8;

    int stage = 0;
    for (int it = 0; it < ITERS; it++) {
        if (it < ITERS - 1) asm volatile("cp.async.wait_group 1;\n");
        else                asm volatile("cp.async.wait_group 0;\n");
        __syncthreads();

        if (it + 2 < ITERS) {
            int nstg = stage + 2; if (nstg >= STAGES) nstg -= STAGES;
            G1_ISSUE(nstg, (it + 2) * GBK);
        }

        uint32_t sA = smem0 + (uint32_t)stage * STAGE_B;
        uint32_t sB = sA + A_BYTES;
#pragma unroll
        for (int ks = 0; ks < GBK; ks += 16) {
            unsigned af[4][4];
#pragma unroll
            for (int mi = 0; mi < 4; mi++)
                ldsm_x4(af[mi][0], af[mi][1], af[mi][2], af[mi][3],
                        sA + ((a_row + mi * 16) * SROW + ks + a_col) * 2);
            unsigned bf[8][2];
#pragma unroll
            for (int ni2 = 0; ni2 < 4; ni2++)
                ldsm_x4(bf[ni2*2][0], bf[ni2*2][1], bf[ni2*2+1][0], bf[ni2*2+1][1],
                        sB + ((b_row + ni2 * 16) * SROW + ks + b_col) * 2);
#pragma unroll
            for (int ni = 0; ni < 8; ni++)
#pragma unroll
                for (int mi = 0; mi < 4; mi++)
                    mma_bf16(acc[mi][ni], af[mi], bf[ni][0], bf[ni][1]);
        }
        if (++stage == STAGES) stage = 0;
    }

    // epilogue: bias + RoPE, write q/k as bf16 [b][h][pos][d]
    const int sel  = warp_n;                 // warp covers one 64-col q/k block
    const int head = (n0 + warp_n * 64) >> 7;
    __nv_bfloat16* const dstbase = sel ? g_k : g_q;
#pragma unroll
    for (int mi = 0; mi < 4; mi++) {
        int rbase = m0 + warp_m * 64 + mi * 16 + g;
#pragma unroll
        for (int ni = 0; ni < 8; ni++) {
            int d  = ni * 8 + tg * 2;        // 0..62 even
            int fi = d >> 1;
            int n  = n0 + warp_n * 64 + d;
            float b0 = bias[n], b1 = bias[n + 1];
#pragma unroll
            for (int rr = 0; rr < 2; rr++) {
                int r = rbase + rr * 8;
                int bb = r >> 9;
                int pos = r & 511;
                float2 cs = g_sc[(pos << 5) + fi];
                float x0 = acc[mi][ni][rr * 2 + 0] + b0;
                float x1 = acc[mi][ni][rr * 2 + 1] + b1;
                float y0 = x0 * cs.x - x1 * cs.y;
                float y1 = x1 * cs.x + x0 * cs.y;
                size_t off = ((((size_t)bb * HEADS + head) * SEQ + pos) * HDIM) + d;
                __nv_bfloat162 p;
                p.x = __float2bfloat16(y0);
                p.y = __float2bfloat16(y1);
                *(__nv_bfloat162*)(dstbase + off) = p;
            }
        }
    }
}

// ---------------- GEMM2: logits = q @ k^T, masks, scale ----------------
__global__ __launch_bounds__(256) void gemm2_kernel(const int* __restrict__ am,
                                                    float* __restrict__ out) {
    const int bh = blockIdx.z;
    const int b  = bh / HEADS;
    const int m0 = blockIdx.y * 64, n0 = blockIdx.x * 64;
    float* outbase = out + (size_t)bh * SEQ * SEQ;
    const int tid = threadIdx.x;

    if (m0 >= n0 + 64) {
        int c4 = tid & 15, r = tid >> 4;
#pragma unroll
        for (int rr = 0; rr < 64; rr += 16) {
            int m = m0 + r + rr;
            float amm = (float)am[b * SEQ + m];
            float4 v;
#pragma unroll
            for (int j = 0; j < 4; j++) {
                int n = n0 + c4 * 4 + j;
                float amn = (float)am[b * SEQ + n];
                float pad = 1.f - amm * amn;
                ((float*)&v)[j] = (0.f - pad * NEG_BIG - NEG_BIG) * 0.125f;
            }
            *(float4*)(outbase + (size_t)m * SEQ + n0 + c4 * 4) = v;
        }
        return;
    }

    __shared__ __nv_bfloat16 Qs[64][72];
    __shared__ __nv_bfloat16 Ks[64][72];
    __shared__ float am_m[64], am_n[64];

    if (tid < 64)        am_m[tid]      = (float)am[b * SEQ + m0 + tid];
    else if (tid < 128)  am_n[tid - 64] = (float)am[b * SEQ + n0 + tid - 64];

    const __nv_bfloat16* qbase = g_q + ((size_t)bh * SEQ + m0) * HDIM;
    const __nv_bfloat16* kbase = g_k + ((size_t)bh * SEQ + n0) * HDIM;
    int pr = tid & 31;
    int rw = tid >> 5;
#pragma unroll
    for (int rr = 0; rr < 64; rr += 8) {
        *(unsigned*)&Qs[rw + rr][pr * 2] = *(const unsigned*)(qbase + (size_t)(rw + rr) * HDIM + pr * 2);
        *(unsigned*)&Ks[rw + rr][pr * 2] = *(const unsigned*)(kbase + (size_t)(rw + rr) * HDIM + pr * 2);
    }
    __syncthreads();

    const int wid = tid >> 5, lane = tid & 31;
    const int wm = wid >> 1, wn = wid & 1;
    const int g = lane >> 2, tg = lane & 3;

    float acc[4][4];
#pragma unroll
    for (int a = 0; a < 4; a++)
#pragma unroll
        for (int c = 0; c < 4; c++) acc[a][c] = 0.f;

#pragma unroll
    for (int ks = 0; ks < 64; ks += 16) {
        unsigned af[4];
        int row = wm * 16 + g;
        af[0] = *(unsigned*)&Qs[row][ks + tg * 2];
        af[1] = *(unsigned*)&Qs[row + 8][ks + tg * 2];
        af[2] = *(unsigned*)&Qs[row][ks + 8 + tg * 2];
        af[3] = *(unsigned*)&Qs[row + 8][ks + 8 + tg * 2];
#pragma unroll
        for (int ni = 0; ni < 4; ni++) {
            int col = wn * 32 + ni * 8 + g;
            unsigned b0 = *(unsigned*)&Ks[col][ks + tg * 2];
            unsigned b1 = *(unsigned*)&Ks[col][ks + 8 + tg * 2];
            mma_bf16(acc[ni], af, b0, b1);
        }
    }

    int rl = wm * 16 + g;
    int r0 = m0 + rl;
    float amm0 = am_m[rl], amm1 = am_m[rl + 8];
#pragma unroll
    for (int ni = 0; ni < 4; ni++) {
        int nl = wn * 32 + ni * 8 + tg * 2;
        int n  = n0 + nl;
        float amn0 = am_n[nl], amn1 = am_n[nl + 1];

        float v00 = acc[ni][0] - (1.f - amm0 * amn0) * NEG_BIG - ((n     < r0) ? NEG_BIG : 0.f);
        float v01 = acc[ni][1] - (1.f - amm0 * amn1) * NEG_BIG - ((n + 1 < r0) ? NEG_BIG : 0.f);
        *(float2*)(outbase + (size_t)r0 * SEQ + n) = make_float2(v00 * 0.125f, v01 * 0.125f);

        int r1 = r0 + 8;
        float v10 = acc[ni][2] - (1.f - amm1 * amn0) * NEG_BIG - ((n     < r1) ? NEG_BIG : 0.f);
        float v11 = acc[ni][3] - (1.f - amm1 * amn1) * NEG_BIG - ((n + 1 < r1) ? NEG_BIG : 0.f);
        *(float2*)(outbase + (size_t)r1 * SEQ + n) = make_float2(v10 * 0.125f, v11 * 0.125f);
    }
}

// ---------------- launch ----------------
extern "C" void kernel_launch(void* const* d_in, const int* in_sizes, int n_in,
                              void* d_out, int out_size) {
    const float* hidden = (const float*)d_in[0];
    const int*   amask  = (const int*)d_in[1];
    const float* W      = (const float*)d_in[2];
    const float* bias   = (const float*)d_in[3];
    float* out = (float*)d_out;

    cudaFuncSetAttribute(gemm1_kernel, cudaFuncAttributeMaxDynamicSharedMemorySize, DYN_SMEM);

    conv_hidden_kernel<<<(M1 * K1 / 4 + 255) / 256, 256>>>(hidden);
    conv_w_kernel<<<dim3(N1 / 32, K1 / 32), dim3(32, 8)>>>(W);
    rope_table_kernel<<<(SEQ * (HDIM/2) + 255) / 256, 256>>>();

    gemm1_kernel<<<dim3(N1 / TN, M1 / TM), 256, DYN_SMEM>>>(bias);
    gemm2_kernel<<<dim3(SEQ / 64, SEQ / 64, BS * HEADS), 256>>>(amask, out);
}

// round 8
// speedup vs baseline: 1.6826x; 1.6826x over previous
#include <cuda_runtime.h>
#include <cuda_bf16.h>
#include <cstdint>

#define BS      16
#define SEQ     512
#define HID     768
#define HEADS   12
#define HDIM    64
#define M1      (BS*SEQ)          // 8192
#define N1      (HEADS*2*HDIM)    // 1536
#define K1      HID               // 768
#define NEG_BIG 1e12f

#define SROW    40                 // padded smem row stride (elements), 80B
#define GBK     32
#define ITERS   (K1/GBK)           // 24
#define STAGES  3
#define TM      128
#define TN      128
#define A_BYTES (TM*SROW*2)        // 10240
#define B_BYTES (TN*SROW*2)        // 10240
#define STAGE_B (A_BYTES + B_BYTES)
#define DYN_SMEM (STAGES*STAGE_B)  // 61440

// ---------------- scratch ----------------
__device__ __nv_bfloat16 g_hidden_bf[M1 * K1];
__device__ __nv_bfloat16 g_Wt[N1 * K1];                 // W transposed [n][k]
__device__ __nv_bfloat16 g_q[BS * HEADS * SEQ * HDIM];  // [b][h][s][d]
__device__ __nv_bfloat16 g_k[BS * HEADS * SEQ * HDIM];
__device__ float2        g_sc[SEQ * (HDIM/2)];

// ---------------- helpers ----------------
__device__ __forceinline__ void mma_bf16(float* c, const unsigned* a, unsigned b0, unsigned b1) {
    asm volatile(
        "mma.sync.aligned.m16n8k16.row.col.f32.bf16.bf16.f32 "
        "{%0,%1,%2,%3}, {%4,%5,%6,%7}, {%8,%9}, {%0,%1,%2,%3};\n"
        : "+f"(c[0]), "+f"(c[1]), "+f"(c[2]), "+f"(c[3])
        : "r"(a[0]), "r"(a[1]), "r"(a[2]), "r"(a[3]), "r"(b0), "r"(b1));
}

__device__ __forceinline__ void ldsm_x4(unsigned& r0, unsigned& r1, unsigned& r2, unsigned& r3,
                                        uint32_t addr) {
    asm volatile("ldmatrix.sync.aligned.m8n8.x4.shared.b16 {%0,%1,%2,%3}, [%4];\n"
                 : "=r"(r0), "=r"(r1), "=r"(r2), "=r"(r3) : "r"(addr));
}

__device__ __forceinline__ void cp16(uint32_t s, const void* g) {
    asm volatile("cp.async.cg.shared.global [%0], [%1], 16;\n" :: "r"(s), "l"(g));
}

// ---------------- prep kernels ----------------
__global__ void conv_hidden_kernel(const float* __restrict__ src) {
    int i = (blockIdx.x * blockDim.x + threadIdx.x) * 4;
    if (i >= M1 * K1) return;
    float4 v = *(const float4*)(src + i);
    __nv_bfloat162 p0, p1;
    p0.x = __float2bfloat16(v.x); p0.y = __float2bfloat16(v.y);
    p1.x = __float2bfloat16(v.z); p1.y = __float2bfloat16(v.w);
    uint2 u; u.x = *(unsigned*)&p0; u.y = *(unsigned*)&p1;
    *(uint2*)(g_hidden_bf + i) = u;
}

__global__ void conv_w_kernel(const float* __restrict__ src) {
    __shared__ float tile[32][33];
    int n0 = blockIdx.x * 32, k0 = blockIdx.y * 32;
    int tx = threadIdx.x, ty = threadIdx.y;
#pragma unroll
    for (int i = 0; i < 32; i += 8)
        tile[ty + i][tx] = src[(size_t)(k0 + ty + i) * N1 + n0 + tx];
    __syncthreads();
#pragma unroll
    for (int i = 0; i < 32; i += 8)
        g_Wt[(size_t)(n0 + ty + i) * K1 + k0 + tx] = __float2bfloat16(tile[tx][ty + i]);
}

__global__ void rope_table_kernel() {
    int i = blockIdx.x * blockDim.x + threadIdx.x;
    if (i >= SEQ * (HDIM/2)) return;
    int pos = i >> 5, fi = i & 31;
    float inv = expf(-(float)fi * 0.28782313662425576f);
    float ang = (float)pos * inv;
    float s, c;
    sincosf(ang, &s, &c);
    g_sc[i] = make_float2(c, s);
}

// ---------------- GEMM1: 128x128 block, warp 64x32 (2m x 4n), 3-stage ----------------
__global__ __launch_bounds__(256, 2) void gemm1_kernel(const float* __restrict__ bias) {
    extern __shared__ __nv_bfloat16 sm[];   // [STAGES][A 128*SROW | B 128*SROW]

    const int tid = threadIdx.x;
    const int wid = tid >> 5, lane = tid & 31;
    const int warp_m = wid & 1, warp_n = wid >> 1;    // 2m x 4n, warp 64x32
    const int g = lane >> 2, tg = lane & 3;
    const int m0 = blockIdx.y * TM, n0 = blockIdx.x * TN;

    float acc[4][4][4];   // [mi][ni][quad]
#pragma unroll
    for (int a = 0; a < 4; a++)
#pragma unroll
        for (int b = 0; b < 4; b++)
#pragma unroll
            for (int c = 0; c < 4; c++) acc[a][b][c] = 0.f;

    const int r0 = tid >> 2, seg = tid & 3;
    const __nv_bfloat16* agp = g_hidden_bf + (size_t)(m0 + r0) * K1 + seg * 8;
    const __nv_bfloat16* bgp = g_Wt       + (size_t)(n0 + r0) * K1 + seg * 8;
    const uint32_t smem0 = (uint32_t)__cvta_generic_to_shared(sm);
    const uint32_t stoff = r0 * (SROW * 2) + seg * 16;

#define G1_ISSUE(stg, kk)  do {                                            \
        uint32_t a = smem0 + (uint32_t)(stg) * STAGE_B + stoff;            \
        uint32_t b = a + A_BYTES;                                          \
        cp16(a,                agp + (kk));                                \
        cp16(a + 64*(SROW*2),  agp + (size_t)64*K1 + (kk));                \
        cp16(b,                bgp + (kk));                                \
        cp16(b + 64*(SROW*2),  bgp + (size_t)64*K1 + (kk));                \
        asm volatile("cp.async.commit_group;\n");                          \
    } while (0)

    G1_ISSUE(0, 0);
    G1_ISSUE(1, GBK);

    const int a_row = warp_m * 64 + (lane & 15);
    const int a_col = (lane >> 4) * 8;
    const int b_row = warp_n * 32 + (lane & 7) + ((lane >> 4) << 3);
    const int b_col = ((lane >> 3) & 1) * 8;

    int stage = 0;
    for (int it = 0; it < ITERS; it++) {
        if (it < ITERS - 1) asm volatile("cp.async.wait_group 1;\n");
        else                asm volatile("cp.async.wait_group 0;\n");
        __syncthreads();

        if (it + 2 < ITERS) {
            int nstg = stage + 2; if (nstg >= STAGES) nstg -= STAGES;
            G1_ISSUE(nstg, (it + 2) * GBK);
        }

        uint32_t sA = smem0 + (uint32_t)stage * STAGE_B;
        uint32_t sB = sA + A_BYTES;
#pragma unroll
        for (int ks = 0; ks < GBK; ks += 16) {
            unsigned af[4][4];
#pragma unroll
            for (int mi = 0; mi < 4; mi++)
                ldsm_x4(af[mi][0], af[mi][1], af[mi][2], af[mi][3],
                        sA + ((a_row + mi * 16) * SROW + ks + a_col) * 2);
            unsigned bf[4][2];
#pragma unroll
            for (int ni2 = 0; ni2 < 2; ni2++)
                ldsm_x4(bf[ni2*2][0], bf[ni2*2][1], bf[ni2*2+1][0], bf[ni2*2+1][1],
                        sB + ((b_row + ni2 * 16) * SROW + ks + b_col) * 2);
#pragma unroll
            for (int ni = 0; ni < 4; ni++)
#pragma unroll
                for (int mi = 0; mi < 4; mi++)
                    mma_bf16(acc[mi][ni], af[mi], bf[ni][0], bf[ni][1]);
        }
        if (++stage == STAGES) stage = 0;
    }

    // epilogue: bias + RoPE, write q/k as bf16 [b][h][pos][d]
    const int nwarp = n0 + warp_n * 32;
    const int head  = nwarp >> 7;
    const int sel   = (nwarp >> 6) & 1;
    const int dbase = nwarp & 63;            // 0 or 32
    __nv_bfloat16* const dstbase = sel ? g_k : g_q;
#pragma unroll
    for (int mi = 0; mi < 4; mi++) {
        int rbase = m0 + warp_m * 64 + mi * 16 + g;
#pragma unroll
        for (int ni = 0; ni < 4; ni++) {
            int d  = dbase + ni * 8 + tg * 2;
            int fi = d >> 1;
            int n  = nwarp + ni * 8 + tg * 2;
            float b0 = bias[n], b1 = bias[n + 1];
#pragma unroll
            for (int rr = 0; rr < 2; rr++) {
                int r = rbase + rr * 8;
                int bb = r >> 9;
                int pos = r & 511;
                float2 cs = g_sc[(pos << 5) + fi];
                float x0 = acc[mi][ni][rr * 2 + 0] + b0;
                float x1 = acc[mi][ni][rr * 2 + 1] + b1;
                float y0 = x0 * cs.x - x1 * cs.y;
                float y1 = x1 * cs.x + x0 * cs.y;
                size_t off = ((((size_t)bb * HEADS + head) * SEQ + pos) * HDIM) + d;
                __nv_bfloat162 p;
                p.x = __float2bfloat16(y0);
                p.y = __float2bfloat16(y1);
                *(__nv_bfloat162*)(dstbase + off) = p;
            }
        }
    }
}

// ---------------- GEMM2: logits = q @ k^T, masks, scale ----------------
__global__ __launch_bounds__(256) void gemm2_kernel(const int* __restrict__ am,
                                                    float* __restrict__ out) {
    const int bh = blockIdx.z;
    const int b  = bh / HEADS;
    const int m0 = blockIdx.y * 64, n0 = blockIdx.x * 64;
    float* outbase = out + (size_t)bh * SEQ * SEQ;
    const int tid = threadIdx.x;

    if (m0 >= n0 + 64) {
        int c4 = tid & 15, r = tid >> 4;
#pragma unroll
        for (int rr = 0; rr < 64; rr += 16) {
            int m = m0 + r + rr;
            float amm = (float)am[b * SEQ + m];
            float4 v;
#pragma unroll
            for (int j = 0; j < 4; j++) {
                int n = n0 + c4 * 4 + j;
                float amn = (float)am[b * SEQ + n];
                float pad = 1.f - amm * amn;
                ((float*)&v)[j] = (0.f - pad * NEG_BIG - NEG_BIG) * 0.125f;
            }
            *(float4*)(outbase + (size_t)m * SEQ + n0 + c4 * 4) = v;
        }
        return;
    }

    __shared__ __nv_bfloat16 Qs[64][72];
    __shared__ __nv_bfloat16 Ks[64][72];
    __shared__ float am_m[64], am_n[64];

    if (tid < 64)        am_m[tid]      = (float)am[b * SEQ + m0 + tid];
    else if (tid < 128)  am_n[tid - 64] = (float)am[b * SEQ + n0 + tid - 64];

    const __nv_bfloat16* qbase = g_q + ((size_t)bh * SEQ + m0) * HDIM;
    const __nv_bfloat16* kbase = g_k + ((size_t)bh * SEQ + n0) * HDIM;
    int pr = tid & 31;
    int rw = tid >> 5;
#pragma unroll
    for (int rr = 0; rr < 64; rr += 8) {
        *(unsigned*)&Qs[rw + rr][pr * 2] = *(const unsigned*)(qbase + (size_t)(rw + rr) * HDIM + pr * 2);
        *(unsigned*)&Ks[rw + rr][pr * 2] = *(const unsigned*)(kbase + (size_t)(rw + rr) * HDIM + pr * 2);
    }
    __syncthreads();

    const int wid = tid >> 5, lane = tid & 31;
    const int wm = wid >> 1, wn = wid & 1;
    const int g = lane >> 2, tg = lane & 3;

    float acc[4][4];
#pragma unroll
    for (int a = 0; a < 4; a++)
#pragma unroll
        for (int c = 0; c < 4; c++) acc[a][c] = 0.f;

#pragma unroll
    for (int ks = 0; ks < 64; ks += 16) {
        unsigned af[4];
        int row = wm * 16 + g;
        af[0] = *(unsigned*)&Qs[row][ks + tg * 2];
        af[1] = *(unsigned*)&Qs[row + 8][ks + tg * 2];
        af[2] = *(unsigned*)&Qs[row][ks + 8 + tg * 2];
        af[3] = *(unsigned*)&Qs[row + 8][ks + 8 + tg * 2];
#pragma unroll
        for (int ni = 0; ni < 4; ni++) {
            int col = wn * 32 + ni * 8 + g;
            unsigned b0 = *(unsigned*)&Ks[col][ks + tg * 2];
            unsigned b1 = *(unsigned*)&Ks[col][ks + 8 + tg * 2];
            mma_bf16(acc[ni], af, b0, b1);
        }
    }

    int rl = wm * 16 + g;
    int r0 = m0 + rl;
    float amm0 = am_m[rl], amm1 = am_m[rl + 8];
#pragma unroll
    for (int ni = 0; ni < 4; ni++) {
        int nl = wn * 32 + ni * 8 + tg * 2;
        int n  = n0 + nl;
        float amn0 = am_n[nl], amn1 = am_n[nl + 1];

        float v00 = acc[ni][0] - (1.f - amm0 * amn0) * NEG_BIG - ((n     < r0) ? NEG_BIG : 0.f);
        float v01 = acc[ni][1] - (1.f - amm0 * amn1) * NEG_BIG - ((n + 1 < r0) ? NEG_BIG : 0.f);
        *(float2*)(outbase + (size_t)r0 * SEQ + n) = make_float2(v00 * 0.125f, v01 * 0.125f);

        int r1 = r0 + 8;
        float v10 = acc[ni][2] - (1.f - amm1 * amn0) * NEG_BIG - ((n     < r1) ? NEG_BIG : 0.f);
        float v11 = acc[ni][3] - (1.f - amm1 * amn1) * NEG_BIG - ((n + 1 < r1) ? NEG_BIG : 0.f);
        *(float2*)(outbase + (size_t)r1 * SEQ + n) = make_float2(v10 * 0.125f, v11 * 0.125f);
    }
}

// ---------------- launch ----------------
extern "C" void kernel_launch(void* const* d_in, const int* in_sizes, int n_in,
                              void* d_out, int out_size) {
    const float* hidden = (const float*)d_in[0];
    const int*   amask  = (const int*)d_in[1];
    const float* W      = (const float*)d_in[2];
    const float* bias   = (const float*)d_in[3];
    float* out = (float*)d_out;

    cudaFuncSetAttribute(gemm1_kernel, cudaFuncAttributeMaxDynamicSharedMemorySize, DYN_SMEM);

    conv_hidden_kernel<<<(M1 * K1 / 4 + 255) / 256, 256>>>(hidden);
    conv_w_kernel<<<dim3(N1 / 32, K1 / 32), dim3(32, 8)>>>(W);
    rope_table_kernel<<<(SEQ * (HDIM/2) + 255) / 256, 256>>>();

    gemm1_kernel<<<dim3(N1 / TN, M1 / TM), 256, DYN_SMEM>>>(bias);
    gemm2_kernel<<<dim3(SEQ / 64, SEQ / 64, BS * HEADS), 256>>>(amask, out);
}

// round 9
// speedup vs baseline: 1.8255x; 1.0850x over previous
#include <cuda_runtime.h>
#include <cuda_bf16.h>
#include <cstdint>

#define BS      16
#define SEQ     512
#define HID     768
#define HEADS   12
#define HDIM    64
#define M1      (BS*SEQ)          // 8192
#define N1      (HEADS*2*HDIM)    // 1536
#define K1      HID               // 768
#define NEG_BIG 1e12f

#define SROW    40                 // gemm1 smem row stride (elements), 80B
#define GBK     32
#define ITERS   (K1/GBK)           // 24
#define STAGES  3

// ---------------- scratch ----------------
__device__ __nv_bfloat16 g_hidden_bf[M1 * K1];
__device__ __nv_bfloat16 g_Wt[N1 * K1];                 // W transposed [n][k]
__device__ __nv_bfloat16 g_q[BS * HEADS * SEQ * HDIM];  // [b][h][s][d]
__device__ __nv_bfloat16 g_k[BS * HEADS * SEQ * HDIM];
__device__ float2        g_sc[SEQ * (HDIM/2)];

// ---------------- helpers ----------------
__device__ __forceinline__ void mma_bf16(float* c, const unsigned* a, unsigned b0, unsigned b1) {
    asm volatile(
        "mma.sync.aligned.m16n8k16.row.col.f32.bf16.bf16.f32 "
        "{%0,%1,%2,%3}, {%4,%5,%6,%7}, {%8,%9}, {%0,%1,%2,%3};\n"
        : "+f"(c[0]), "+f"(c[1]), "+f"(c[2]), "+f"(c[3])
        : "r"(a[0]), "r"(a[1]), "r"(a[2]), "r"(a[3]), "r"(b0), "r"(b1));
}

__device__ __forceinline__ void ldsm_x4(unsigned& r0, unsigned& r1, unsigned& r2, unsigned& r3,
                                        uint32_t addr) {
    asm volatile("ldmatrix.sync.aligned.m8n8.x4.shared.b16 {%0,%1,%2,%3}, [%4];\n"
                 : "=r"(r0), "=r"(r1), "=r"(r2), "=r"(r3) : "r"(addr));
}

__device__ __forceinline__ void cp16(uint32_t s, const void* g) {
    asm volatile("cp.async.cg.shared.global [%0], [%1], 16;\n" :: "r"(s), "l"(g));
}

// ---------------- prep kernels ----------------
__global__ void conv_hidden_kernel(const float* __restrict__ src) {
    int i = (blockIdx.x * blockDim.x + threadIdx.x) * 4;
    if (i >= M1 * K1) return;
    float4 v = *(const float4*)(src + i);
    __nv_bfloat162 p0, p1;
    p0.x = __float2bfloat16(v.x); p0.y = __float2bfloat16(v.y);
    p1.x = __float2bfloat16(v.z); p1.y = __float2bfloat16(v.w);
    uint2 u; u.x = *(unsigned*)&p0; u.y = *(unsigned*)&p1;
    *(uint2*)(g_hidden_bf + i) = u;
}

__global__ void conv_w_kernel(const float* __restrict__ src) {
    __shared__ float tile[32][33];
    int n0 = blockIdx.x * 32, k0 = blockIdx.y * 32;
    int tx = threadIdx.x, ty = threadIdx.y;
#pragma unroll
    for (int i = 0; i < 32; i += 8)
        tile[ty + i][tx] = src[(size_t)(k0 + ty + i) * N1 + n0 + tx];
    __syncthreads();
#pragma unroll
    for (int i = 0; i < 32; i += 8)
        g_Wt[(size_t)(n0 + ty + i) * K1 + k0 + tx] = __float2bfloat16(tile[tx][ty + i]);
}

__global__ void rope_table_kernel() {
    int i = blockIdx.x * blockDim.x + threadIdx.x;
    if (i >= SEQ * (HDIM/2)) return;
    int pos = i >> 5, fi = i & 31;
    float inv = expf(-(float)fi * 0.28782313662425576f);
    float ang = (float)pos * inv;
    float s, c;
    sincosf(ang, &s, &c);
    g_sc[i] = make_float2(c, s);
}

// ---------------- GEMM1: 64x128 block, warp 32x32, 3-stage (R6 winner) ----------------
__global__ __launch_bounds__(256, 3) void gemm1_kernel(const float* __restrict__ bias) {
    __shared__ __nv_bfloat16 As[STAGES][64 * SROW];
    __shared__ __nv_bfloat16 Bs[STAGES][128 * SROW];

    const int tid = threadIdx.x;
    const int wid = tid >> 5, lane = tid & 31;
    const int warp_m = wid & 1, warp_n = wid >> 1;
    const int g = lane >> 2, tg = lane & 3;
    const int m0 = blockIdx.y * 64, n0 = blockIdx.x * 128;

    float acc[2][4][4];
#pragma unroll
    for (int a = 0; a < 2; a++)
#pragma unroll
        for (int b = 0; b < 4; b++)
#pragma unroll
            for (int c = 0; c < 4; c++) acc[a][b][c] = 0.f;

    const int r0 = tid >> 2, seg = tid & 3;
    const __nv_bfloat16* agp = g_hidden_bf + (size_t)(m0 + r0) * K1 + seg * 8;
    const __nv_bfloat16* bgp = g_Wt       + (size_t)(n0 + r0) * K1 + seg * 8;
    const uint32_t sA0 = (uint32_t)__cvta_generic_to_shared(&As[0][0]);
    const uint32_t sB0 = (uint32_t)__cvta_generic_to_shared(&Bs[0][0]);
    const uint32_t stoff = r0 * (SROW * 2) + seg * 16;

#define G1_ISSUE(stg, kk)  do {                                            \
        uint32_t a = sA0 + (uint32_t)(stg) * (64*SROW*2)  + stoff;         \
        uint32_t b = sB0 + (uint32_t)(stg) * (128*SROW*2) + stoff;         \
        cp16(a, agp + (kk));                                               \
        cp16(b, bgp + (kk));                                               \
        cp16(b + 64*(SROW*2), bgp + (size_t)64*K1 + (kk));                 \
        asm volatile("cp.async.commit_group;\n");                          \
    } while (0)

    G1_ISSUE(0, 0);
    G1_ISSUE(1, GBK);

    const int a_row = warp_m * 32 + (lane & 15);
    const int a_col = (lane >> 4) * 8;
    const int b_row = warp_n * 32 + (lane & 7) + ((lane >> 4) << 3);
    const int b_col = ((lane >> 3) & 1) * 8;

    int stage = 0;
    for (int it = 0; it < ITERS; it++) {
        if (it < ITERS - 1) asm volatile("cp.async.wait_group 1;\n");
        else                asm volatile("cp.async.wait_group 0;\n");
        __syncthreads();

        if (it + 2 < ITERS) {
            int nstg = stage + 2; if (nstg >= STAGES) nstg -= STAGES;
            G1_ISSUE(nstg, (it + 2) * GBK);
        }

        uint32_t sA = sA0 + (uint32_t)stage * (64*SROW*2);
        uint32_t sB = sB0 + (uint32_t)stage * (128*SROW*2);
#pragma unroll
        for (int ks = 0; ks < GBK; ks += 16) {
            unsigned af[2][4];
#pragma unroll
            for (int mi = 0; mi < 2; mi++)
                ldsm_x4(af[mi][0], af[mi][1], af[mi][2], af[mi][3],
                        sA + ((a_row + mi * 16) * SROW + ks + a_col) * 2);
            unsigned bf[4][2];
#pragma unroll
            for (int ni2 = 0; ni2 < 2; ni2++)
                ldsm_x4(bf[ni2*2][0], bf[ni2*2][1], bf[ni2*2+1][0], bf[ni2*2+1][1],
                        sB + ((b_row + ni2 * 16) * SROW + ks + b_col) * 2);
#pragma unroll
            for (int ni = 0; ni < 4; ni++)
#pragma unroll
                for (int mi = 0; mi < 2; mi++)
                    mma_bf16(acc[mi][ni], af[mi], bf[ni][0], bf[ni][1]);
        }
        if (++stage == STAGES) stage = 0;
    }

#pragma unroll
    for (int mi = 0; mi < 2; mi++) {
        int rbase = m0 + warp_m * 32 + mi * 16 + g;
#pragma unroll
        for (int ni = 0; ni < 4; ni++) {
            int n = n0 + warp_n * 32 + ni * 8 + tg * 2;
            int head = n >> 7;
            int sel  = (n >> 6) & 1;
            int d    = n & 63;
            int fi   = d >> 1;
            float b0 = bias[n], b1 = bias[n + 1];
            __nv_bfloat16* dst = sel ? g_k : g_q;
#pragma unroll
            for (int rr = 0; rr < 2; rr++) {
                int r = rbase + rr * 8;
                int bb = r >> 9;
                int pos = r & 511;
                float2 cs = g_sc[(pos << 5) + fi];
                float x0 = acc[mi][ni][rr * 2 + 0] + b0;
                float x1 = acc[mi][ni][rr * 2 + 1] + b1;
                float y0 = x0 * cs.x - x1 * cs.y;
                float y1 = x1 * cs.x + x0 * cs.y;
                size_t off = ((((size_t)bb * HEADS + head) * SEQ + pos) * HDIM) + d;
                __nv_bfloat162 p;
                p.x = __float2bfloat16(y0);
                p.y = __float2bfloat16(y1);
                *(__nv_bfloat162*)(dst + off) = p;
            }
        }
    }
}

// ---------------- GEMM2: 128x128 tiles, warp 64x32, K=64 single pass ----------------
#define QROW 72
__global__ __launch_bounds__(256) void gemm2_kernel(const int* __restrict__ am,
                                                    float* __restrict__ out) {
    const int bh = blockIdx.z;
    const int b  = bh / HEADS;
    const int m0 = blockIdx.y * 128, n0 = blockIdx.x * 128;
    float* outbase = out + (size_t)bh * SEQ * SEQ;
    const int tid = threadIdx.x;

    if (m0 >= n0 + 128) {
        // fully below the diagonal: skip compute, write masked values
        int c4 = tid & 31, r = tid >> 5;   // 32 16B segs/row, 8 rows per pass
        float amn[4];
#pragma unroll
        for (int j = 0; j < 4; j++) amn[j] = (float)am[b * SEQ + n0 + c4 * 4 + j];
#pragma unroll
        for (int rr = 0; rr < 128; rr += 8) {
            int m = m0 + r + rr;
            float amm = (float)am[b * SEQ + m];
            float4 v;
#pragma unroll
            for (int j = 0; j < 4; j++)
                ((float*)&v)[j] = (0.f - (1.f - amm * amn[j]) * NEG_BIG - NEG_BIG) * 0.125f;
            *(float4*)(outbase + (size_t)m * SEQ + n0 + c4 * 4) = v;
        }
        return;
    }

    __shared__ __nv_bfloat16 Qs[128][QROW];
    __shared__ __nv_bfloat16 Ks[128][QROW];
    __shared__ float am_m[128], am_n[128];

    if (tid < 128) am_m[tid] = (float)am[b * SEQ + m0 + tid];
    else           am_n[tid - 128] = (float)am[b * SEQ + n0 + tid - 128];

    const __nv_bfloat16* qbase = g_q + ((size_t)bh * SEQ + m0) * HDIM;
    const __nv_bfloat16* kbase = g_k + ((size_t)bh * SEQ + n0) * HDIM;
    {
        int rw = tid >> 3, sg = tid & 7;    // 32 rows/pass, 8x16B per 128B row
#pragma unroll
        for (int rr = 0; rr < 128; rr += 32) {
            *(uint4*)&Qs[rw + rr][sg * 8] = *(const uint4*)(qbase + (size_t)(rw + rr) * HDIM + sg * 8);
            *(uint4*)&Ks[rw + rr][sg * 8] = *(const uint4*)(kbase + (size_t)(rw + rr) * HDIM + sg * 8);
        }
    }
    __syncthreads();

    const int wid = tid >> 5, lane = tid & 31;
    const int warp_m = wid & 1, warp_n = wid >> 1;   // 2m x 4n, warp 64x32
    const int g = lane >> 2, tg = lane & 3;

    float acc[4][4][4];
#pragma unroll
    for (int a = 0; a < 4; a++)
#pragma unroll
        for (int c = 0; c < 4; c++)
#pragma unroll
            for (int d = 0; d < 4; d++) acc[a][c][d] = 0.f;

    const uint32_t sQ = (uint32_t)__cvta_generic_to_shared(&Qs[0][0]);
    const uint32_t sK = (uint32_t)__cvta_generic_to_shared(&Ks[0][0]);
    const int a_row = warp_m * 64 + (lane & 15);
    const int a_col = (lane >> 4) * 8;
    const int b_row = warp_n * 32 + (lane & 7) + ((lane >> 4) << 3);
    const int b_col = ((lane >> 3) & 1) * 8;

#pragma unroll
    for (int ks = 0; ks < HDIM; ks += 16) {
        unsigned af[4][4];
#pragma unroll
        for (int mi = 0; mi < 4; mi++)
            ldsm_x4(af[mi][0], af[mi][1], af[mi][2], af[mi][3],
                    sQ + ((a_row + mi * 16) * QROW + ks + a_col) * 2);
        unsigned bf[4][2];
#pragma unroll
        for (int ni2 = 0; ni2 < 2; ni2++)
            ldsm_x4(bf[ni2*2][0], bf[ni2*2][1], bf[ni2*2+1][0], bf[ni2*2+1][1],
                    sK + ((b_row + ni2 * 16) * QROW + ks + b_col) * 2);
#pragma unroll
        for (int ni = 0; ni < 4; ni++)
#pragma unroll
            for (int mi = 0; mi < 4; mi++)
                mma_bf16(acc[mi][ni], af[mi], bf[ni][0], bf[ni][1]);
    }

    // epilogue: masks + scale
#pragma unroll
    for (int mi = 0; mi < 4; mi++) {
        int rl = warp_m * 64 + mi * 16 + g;
        int r0 = m0 + rl;
        float amm0 = am_m[rl], amm1 = am_m[rl + 8];
#pragma unroll
        for (int ni = 0; ni < 4; ni++) {
            int nl = warp_n * 32 + ni * 8 + tg * 2;
            int n  = n0 + nl;
            float amn0 = am_n[nl], amn1 = am_n[nl + 1];

            float v00 = acc[mi][ni][0] - (1.f - amm0 * amn0) * NEG_BIG - ((n     < r0) ? NEG_BIG : 0.f);
            float v01 = acc[mi][ni][1] - (1.f - amm0 * amn1) * NEG_BIG - ((n + 1 < r0) ? NEG_BIG : 0.f);
            *(float2*)(outbase + (size_t)r0 * SEQ + n) = make_float2(v00 * 0.125f, v01 * 0.125f);

            int r1 = r0 + 8;
            float v10 = acc[mi][ni][2] - (1.f - amm1 * amn0) * NEG_BIG - ((n     < r1) ? NEG_BIG : 0.f);
            float v11 = acc[mi][ni][3] - (1.f - amm1 * amn1) * NEG_BIG - ((n + 1 < r1) ? NEG_BIG : 0.f);
            *(float2*)(outbase + (size_t)r1 * SEQ + n) = make_float2(v10 * 0.125f, v11 * 0.125f);
        }
    }
}

// ---------------- launch ----------------
extern "C" void kernel_launch(void* const* d_in, const int* in_sizes, int n_in,
                              void* d_out, int out_size) {
    const float* hidden = (const float*)d_in[0];
    const int*   amask  = (const int*)d_in[1];
    const float* W      = (const float*)d_in[2];
    const float* bias   = (const float*)d_in[3];
    float* out = (float*)d_out;

    conv_hidden_kernel<<<(M1 * K1 / 4 + 255) / 256, 256>>>(hidden);
    conv_w_kernel<<<dim3(N1 / 32, K1 / 32), dim3(32, 8)>>>(W);
    rope_table_kernel<<<(SEQ * (HDIM/2) + 255) / 256, 256>>>();

    gemm1_kernel<<<dim3(N1 / 128, M1 / 64), 256>>>(bias);
    gemm2_kernel<<<dim3(SEQ / 128, SEQ / 128, BS * HEADS), 256>>>(amask, out);
}

// round 10
// speedup vs baseline: 1.8310x; 1.0030x over previous
#include <cuda_runtime.h>
#include <cuda_bf16.h>
#include <cstdint>

#define BS      16
#define SEQ     512
#define HID     768
#define HEADS   12
#define HDIM    64
#define M1      (BS*SEQ)          // 8192
#define N1      (HEADS*2*HDIM)    // 1536
#define K1      HID               // 768
#define NEG_BIG 1e12f

#define SROW    40                 // gemm1 smem row stride (elements), 80B
#define GBK     32
#define ITERS   (K1/GBK)           // 24
#define STAGES  3

// ---------------- scratch ----------------
__device__ __nv_bfloat16 g_hidden_bf[M1 * K1];
__device__ __nv_bfloat16 g_Wt[N1 * K1];                 // W transposed [n][k]
__device__ __nv_bfloat16 g_q[BS * HEADS * SEQ * HDIM];  // [b][h][s][d]
__device__ __nv_bfloat16 g_k[BS * HEADS * SEQ * HDIM];
__device__ float2        g_sc[SEQ * (HDIM/2)];

// ---------------- helpers ----------------
__device__ __forceinline__ void mma_bf16(float* c, const unsigned* a, unsigned b0, unsigned b1) {
    asm volatile(
        "mma.sync.aligned.m16n8k16.row.col.f32.bf16.bf16.f32 "
        "{%0,%1,%2,%3}, {%4,%5,%6,%7}, {%8,%9}, {%0,%1,%2,%3};\n"
        : "+f"(c[0]), "+f"(c[1]), "+f"(c[2]), "+f"(c[3])
        : "r"(a[0]), "r"(a[1]), "r"(a[2]), "r"(a[3]), "r"(b0), "r"(b1));
}

__device__ __forceinline__ void ldsm_x4(unsigned& r0, unsigned& r1, unsigned& r2, unsigned& r3,
                                        uint32_t addr) {
    asm volatile("ldmatrix.sync.aligned.m8n8.x4.shared.b16 {%0,%1,%2,%3}, [%4];\n"
                 : "=r"(r0), "=r"(r1), "=r"(r2), "=r"(r3) : "r"(addr));
}

__device__ __forceinline__ void cp16(uint32_t s, const void* g) {
    asm volatile("cp.async.cg.shared.global [%0], [%1], 16;\n" :: "r"(s), "l"(g));
}

// ---------------- prep kernels ----------------
__global__ void conv_hidden_kernel(const float* __restrict__ src) {
    int i = (blockIdx.x * blockDim.x + threadIdx.x) * 4;
    if (i >= M1 * K1) return;
    float4 v = *(const float4*)(src + i);
    __nv_bfloat162 p0, p1;
    p0.x = __float2bfloat16(v.x); p0.y = __float2bfloat16(v.y);
    p1.x = __float2bfloat16(v.z); p1.y = __float2bfloat16(v.w);
    uint2 u; u.x = *(unsigned*)&p0; u.y = *(unsigned*)&p1;
    *(uint2*)(g_hidden_bf + i) = u;
}

__global__ void conv_w_kernel(const float* __restrict__ src) {
    __shared__ float tile[32][33];
    int n0 = blockIdx.x * 32, k0 = blockIdx.y * 32;
    int tx = threadIdx.x, ty = threadIdx.y;
#pragma unroll
    for (int i = 0; i < 32; i += 8)
        tile[ty + i][tx] = src[(size_t)(k0 + ty + i) * N1 + n0 + tx];
    __syncthreads();
#pragma unroll
    for (int i = 0; i < 32; i += 8)
        g_Wt[(size_t)(n0 + ty + i) * K1 + k0 + tx] = __float2bfloat16(tile[tx][ty + i]);
}

__global__ void rope_table_kernel() {
    int i = blockIdx.x * blockDim.x + threadIdx.x;
    if (i >= SEQ * (HDIM/2)) return;
    int pos = i >> 5, fi = i & 31;
    float inv = expf(-(float)fi * 0.28782313662425576f);
    float ang = (float)pos * inv;
    float s, c;
    sincosf(ang, &s, &c);
    g_sc[i] = make_float2(c, s);
}

// ---------------- fill kernel: fully-causal-masked 128x128 tiles (pure writes) ----------------
__global__ __launch_bounds__(256) void fill_kernel(const int* __restrict__ am,
                                                   float* __restrict__ out) {
    // 6 tiles below the 128-diagonal: (my,nx) with my > nx
    const int lutm[6] = {1, 2, 2, 3, 3, 3};
    const int lutn[6] = {0, 0, 1, 0, 1, 2};
    const int m0 = lutm[blockIdx.x] * 128;
    const int n0 = lutn[blockIdx.x] * 128;
    const int bh = blockIdx.y;
    const int b  = bh / HEADS;
    float* outbase = out + (size_t)bh * SEQ * SEQ;
    const int tid = threadIdx.x;
    const int c4 = tid & 31, r = tid >> 5;

    float amn[4];
#pragma unroll
    for (int j = 0; j < 4; j++) amn[j] = (float)am[b * SEQ + n0 + c4 * 4 + j];
#pragma unroll
    for (int rr = 0; rr < 128; rr += 8) {
        int m = m0 + r + rr;
        float amm = (float)am[b * SEQ + m];
        float4 v;
#pragma unroll
        for (int j = 0; j < 4; j++)
            ((float*)&v)[j] = (0.f - (1.f - amm * amn[j]) * NEG_BIG - NEG_BIG) * 0.125f;
        *(float4*)(outbase + (size_t)m * SEQ + n0 + c4 * 4) = v;
    }
}

// ---------------- GEMM1: 64x128 block, warp 32x32, 3-stage (R6/R9 winner) ----------------
__global__ __launch_bounds__(256, 3) void gemm1_kernel(const float* __restrict__ bias) {
    __shared__ __nv_bfloat16 As[STAGES][64 * SROW];
    __shared__ __nv_bfloat16 Bs[STAGES][128 * SROW];

    const int tid = threadIdx.x;
    const int wid = tid >> 5, lane = tid & 31;
    const int warp_m = wid & 1, warp_n = wid >> 1;
    const int g = lane >> 2, tg = lane & 3;
    const int m0 = blockIdx.y * 64, n0 = blockIdx.x * 128;

    float acc[2][4][4];
#pragma unroll
    for (int a = 0; a < 2; a++)
#pragma unroll
        for (int b = 0; b < 4; b++)
#pragma unroll
            for (int c = 0; c < 4; c++) acc[a][b][c] = 0.f;

    const int r0 = tid >> 2, seg = tid & 3;
    const __nv_bfloat16* agp = g_hidden_bf + (size_t)(m0 + r0) * K1 + seg * 8;
    const __nv_bfloat16* bgp = g_Wt       + (size_t)(n0 + r0) * K1 + seg * 8;
    const uint32_t sA0 = (uint32_t)__cvta_generic_to_shared(&As[0][0]);
    const uint32_t sB0 = (uint32_t)__cvta_generic_to_shared(&Bs[0][0]);
    const uint32_t stoff = r0 * (SROW * 2) + seg * 16;

#define G1_ISSUE(stg, kk)  do {                                            \
        uint32_t a = sA0 + (uint32_t)(stg) * (64*SROW*2)  + stoff;         \
        uint32_t b = sB0 + (uint32_t)(stg) * (128*SROW*2) + stoff;         \
        cp16(a, agp + (kk));                                               \
        cp16(b, bgp + (kk));                                               \
        cp16(b + 64*(SROW*2), bgp + (size_t)64*K1 + (kk));                 \
        asm volatile("cp.async.commit_group;\n");                          \
    } while (0)

    G1_ISSUE(0, 0);
    G1_ISSUE(1, GBK);

    const int a_row = warp_m * 32 + (lane & 15);
    const int a_col = (lane >> 4) * 8;
    const int b_row = warp_n * 32 + (lane & 7) + ((lane >> 4) << 3);
    const int b_col = ((lane >> 3) & 1) * 8;

    int stage = 0;
    for (int it = 0; it < ITERS; it++) {
        if (it < ITERS - 1) asm volatile("cp.async.wait_group 1;\n");
        else                asm volatile("cp.async.wait_group 0;\n");
        __syncthreads();

        if (it + 2 < ITERS) {
            int nstg = stage + 2; if (nstg >= STAGES) nstg -= STAGES;
            G1_ISSUE(nstg, (it + 2) * GBK);
        }

        uint32_t sA = sA0 + (uint32_t)stage * (64*SROW*2);
        uint32_t sB = sB0 + (uint32_t)stage * (128*SROW*2);
#pragma unroll
        for (int ks = 0; ks < GBK; ks += 16) {
            unsigned af[2][4];
#pragma unroll
            for (int mi = 0; mi < 2; mi++)
                ldsm_x4(af[mi][0], af[mi][1], af[mi][2], af[mi][3],
                        sA + ((a_row + mi * 16) * SROW + ks + a_col) * 2);
            unsigned bf[4][2];
#pragma unroll
            for (int ni2 = 0; ni2 < 2; ni2++)
                ldsm_x4(bf[ni2*2][0], bf[ni2*2][1], bf[ni2*2+1][0], bf[ni2*2+1][1],
                        sB + ((b_row + ni2 * 16) * SROW + ks + b_col) * 2);
#pragma unroll
            for (int ni = 0; ni < 4; ni++)
#pragma unroll
                for (int mi = 0; mi < 2; mi++)
                    mma_bf16(acc[mi][ni], af[mi], bf[ni][0], bf[ni][1]);
        }
        if (++stage == STAGES) stage = 0;
    }

#pragma unroll
    for (int mi = 0; mi < 2; mi++) {
        int rbase = m0 + warp_m * 32 + mi * 16 + g;
#pragma unroll
        for (int ni = 0; ni < 4; ni++) {
            int n = n0 + warp_n * 32 + ni * 8 + tg * 2;
            int head = n >> 7;
            int sel  = (n >> 6) & 1;
            int d    = n & 63;
            int fi   = d >> 1;
            float b0 = bias[n], b1 = bias[n + 1];
            __nv_bfloat16* dst = sel ? g_k : g_q;
#pragma unroll
            for (int rr = 0; rr < 2; rr++) {
                int r = rbase + rr * 8;
                int bb = r >> 9;
                int pos = r & 511;
                float2 cs = g_sc[(pos << 5) + fi];
                float x0 = acc[mi][ni][rr * 2 + 0] + b0;
                float x1 = acc[mi][ni][rr * 2 + 1] + b1;
                float y0 = x0 * cs.x - x1 * cs.y;
                float y1 = x1 * cs.x + x0 * cs.y;
                size_t off = ((((size_t)bb * HEADS + head) * SEQ + pos) * HDIM) + d;
                __nv_bfloat162 p;
                p.x = __float2bfloat16(y0);
                p.y = __float2bfloat16(y1);
                *(__nv_bfloat162*)(dst + off) = p;
            }
        }
    }
}

// ---------------- GEMM2: 128x128 tiles, warp 64x32, K=64 single pass ----------------
#define QROW 72
__global__ __launch_bounds__(256) void gemm2_kernel(const int* __restrict__ am,
                                                    float* __restrict__ out) {
    const int bh = blockIdx.z;
    const int b  = bh / HEADS;
    const int m0 = blockIdx.y * 128, n0 = blockIdx.x * 128;
    float* outbase = out + (size_t)bh * SEQ * SEQ;
    const int tid = threadIdx.x;

    if (m0 >= n0 + 128) return;   // handled by fill_kernel

    __shared__ __nv_bfloat16 Qs[128][QROW];
    __shared__ __nv_bfloat16 Ks[128][QROW];
    __shared__ float am_m[128], am_n[128];

    if (tid < 128) am_m[tid] = (float)am[b * SEQ + m0 + tid];
    else           am_n[tid - 128] = (float)am[b * SEQ + n0 + tid - 128];

    const __nv_bfloat16* qbase = g_q + ((size_t)bh * SEQ + m0) * HDIM;
    const __nv_bfloat16* kbase = g_k + ((size_t)bh * SEQ + n0) * HDIM;
    {
        int rw = tid >> 3, sg = tid & 7;
#pragma unroll
        for (int rr = 0; rr < 128; rr += 32) {
            *(uint4*)&Qs[rw + rr][sg * 8] = *(const uint4*)(qbase + (size_t)(rw + rr) * HDIM + sg * 8);
            *(uint4*)&Ks[rw + rr][sg * 8] = *(const uint4*)(kbase + (size_t)(rw + rr) * HDIM + sg * 8);
        }
    }
    __syncthreads();

    const int wid = tid >> 5, lane = tid & 31;
    const int warp_m = wid & 1, warp_n = wid >> 1;
    const int g = lane >> 2, tg = lane & 3;

    float acc[4][4][4];
#pragma unroll
    for (int a = 0; a < 4; a++)
#pragma unroll
        for (int c = 0; c < 4; c++)
#pragma unroll
            for (int d = 0; d < 4; d++) acc[a][c][d] = 0.f;

    const uint32_t sQ = (uint32_t)__cvta_generic_to_shared(&Qs[0][0]);
    const uint32_t sK = (uint32_t)__cvta_generic_to_shared(&Ks[0][0]);
    const int a_row = warp_m * 64 + (lane & 15);
    const int a_col = (lane >> 4) * 8;
    const int b_row = warp_n * 32 + (lane & 7) + ((lane >> 4) << 3);
    const int b_col = ((lane >> 3) & 1) * 8;

#pragma unroll
    for (int ks = 0; ks < HDIM; ks += 16) {
        unsigned af[4][4];
#pragma unroll
        for (int mi = 0; mi < 4; mi++)
            ldsm_x4(af[mi][0], af[mi][1], af[mi][2], af[mi][3],
                    sQ + ((a_row + mi * 16) * QROW + ks + a_col) * 2);
        unsigned bf[4][2];
#pragma unroll
        for (int ni2 = 0; ni2 < 2; ni2++)
            ldsm_x4(bf[ni2*2][0], bf[ni2*2][1], bf[ni2*2+1][0], bf[ni2*2+1][1],
                    sK + ((b_row + ni2 * 16) * QROW + ks + b_col) * 2);
#pragma unroll
        for (int ni = 0; ni < 4; ni++)
#pragma unroll
            for (int mi = 0; mi < 4; mi++)
                mma_bf16(acc[mi][ni], af[mi], bf[ni][0], bf[ni][1]);
    }

#pragma unroll
    for (int mi = 0; mi < 4; mi++) {
        int rl = warp_m * 64 + mi * 16 + g;
        int r0 = m0 + rl;
        float amm0 = am_m[rl], amm1 = am_m[rl + 8];
#pragma unroll
        for (int ni = 0; ni < 4; ni++) {
            int nl = warp_n * 32 + ni * 8 + tg * 2;
            int n  = n0 + nl;
            float amn0 = am_n[nl], amn1 = am_n[nl + 1];

            float v00 = acc[mi][ni][0] - (1.f - amm0 * amn0) * NEG_BIG - ((n     < r0) ? NEG_BIG : 0.f);
            float v01 = acc[mi][ni][1] - (1.f - amm0 * amn1) * NEG_BIG - ((n + 1 < r0) ? NEG_BIG : 0.f);
            *(float2*)(outbase + (size_t)r0 * SEQ + n) = make_float2(v00 * 0.125f, v01 * 0.125f);

            int r1 = r0 + 8;
            float v10 = acc[mi][ni][2] - (1.f - amm1 * amn0) * NEG_BIG - ((n     < r1) ? NEG_BIG : 0.f);
            float v11 = acc[mi][ni][3] - (1.f - amm1 * amn1) * NEG_BIG - ((n + 1 < r1) ? NEG_BIG : 0.f);
            *(float2*)(outbase + (size_t)r1 * SEQ + n) = make_float2(v10 * 0.125f, v11 * 0.125f);
        }
    }
}

// ---------------- launch: fork/join side stream for overlap ----------------
extern "C" void kernel_launch(void* const* d_in, const int* in_sizes, int n_in,
                              void* d_out, int out_size) {
    const float* hidden = (const float*)d_in[0];
    const int*   amask  = (const int*)d_in[1];
    const float* W      = (const float*)d_in[2];
    const float* bias   = (const float*)d_in[3];
    float* out = (float*)d_out;

    static cudaStream_t s2 = nullptr;
    static cudaEvent_t evF = nullptr, ev1 = nullptr, ev2 = nullptr;
    if (s2 == nullptr) {
        cudaStreamCreateWithFlags(&s2, cudaStreamNonBlocking);
        cudaEventCreateWithFlags(&evF, cudaEventDisableTiming);
        cudaEventCreateWithFlags(&ev1, cudaEventDisableTiming);
        cudaEventCreateWithFlags(&ev2, cudaEventDisableTiming);
    }

    // fork side stream from the main (capture) stream
    cudaEventRecord(evF, 0);
    cudaStreamWaitEvent(s2, evF, 0);

    // main stream: hidden conversion (biggest prep)
    conv_hidden_kernel<<<(M1 * K1 / 4 + 255) / 256, 256>>>(hidden);

    // side stream: W transpose + rope table, then masked-tile fill
    conv_w_kernel<<<dim3(N1 / 32, K1 / 32), dim3(32, 8), 0, s2>>>(W);
    rope_table_kernel<<<(SEQ * (HDIM/2) + 255) / 256, 256, 0, s2>>>();
    cudaEventRecord(ev1, s2);
    fill_kernel<<<dim3(6, BS * HEADS), 256, 0, s2>>>(amask, out);
    cudaEventRecord(ev2, s2);

    // gemm1 needs conv_hidden (same stream) + conv_w/rope (ev1)
    cudaStreamWaitEvent(0, ev1, 0);
    gemm1_kernel<<<dim3(N1 / 128, M1 / 64), 256>>>(bias);

    // gemm2 needs gemm1 (same stream); join fill (ev2) so the graph end depends on it
    cudaStreamWaitEvent(0, ev2, 0);
    gemm2_kernel<<<dim3(SEQ / 128, SEQ / 128, BS * HEADS), 256>>>(amask, out);
}